// round 2
// baseline (speedup 1.0000x reference)
#include <cuda_runtime.h>

#define NEXP 2048
#define NDICT 65536
#define NPIX 1600
#define KTOP 10
#define BM 128
#define BN 128
#define BK 16

// Scratch (device globals: allocation-free per harness rules)
__device__ float g_cos[(size_t)NEXP * NDICT];   // 512 MB cos-sim matrix
__device__ float g_mq[NEXP];
__device__ float g_iq[NEXP];
__device__ float g_md[NDICT];
__device__ float g_id[NDICT];

// ---------------------------------------------------------------------------
// Per-row mean and inverse centered-norm:  inv = rsqrt(sum(x^2) - mean*sum(x))
// which == 1/||x - mean(x)||.  which=0 -> experimental (g_mq/g_iq),
// which=1 -> dictionary (g_md/g_id).
// ---------------------------------------------------------------------------
__global__ void rowstats_kernel(const float* __restrict__ X, int which) {
    int row = blockIdx.x;
    const float* x = X + (size_t)row * NPIX;
    float s = 0.f, s2 = 0.f;
    for (int i = threadIdx.x; i < NPIX; i += blockDim.x) {
        float v = x[i];
        s += v;
        s2 += v * v;
    }
#pragma unroll
    for (int o = 16; o > 0; o >>= 1) {
        s  += __shfl_down_sync(0xffffffffu, s, o);
        s2 += __shfl_down_sync(0xffffffffu, s2, o);
    }
    __shared__ float sh_s[8], sh_s2[8];
    int w = threadIdx.x >> 5, l = threadIdx.x & 31;
    if (l == 0) { sh_s[w] = s; sh_s2[w] = s2; }
    __syncthreads();
    if (threadIdx.x == 0) {
        float ts = 0.f, ts2 = 0.f;
#pragma unroll
        for (int i = 0; i < 8; i++) { ts += sh_s[i]; ts2 += sh_s2[i]; }
        float m = ts / (float)NPIX;
        float inv = rsqrtf(ts2 - m * ts);
        if (which == 0) { g_mq[row] = m; g_iq[row] = inv; }
        else            { g_md[row] = m; g_id[row] = inv; }
    }
}

// ---------------------------------------------------------------------------
// C[m][n] = dot(A[m,:], B[n,:]) with fused centering/normalization epilogue:
//   cos = (dot - NPIX*mq*md) * iq * id   -> g_cos
// 128x128x16 tiles, 256 threads, 8x8 per thread, double-buffered smem,
// smem stored transposed [BK][BM] for conflict-free float4 fragment reads.
// ---------------------------------------------------------------------------
__global__ void __launch_bounds__(256, 2)
gemm_kernel(const float* __restrict__ A, const float* __restrict__ B) {
    __shared__ float As[2][BK][BM];
    __shared__ float Bs[2][BK][BN];

    const int tid = threadIdx.x;
    const int m_base = blockIdx.y * BM;
    const int n_base = blockIdx.x * BN;

    // Loader mapping: 2048 floats per tile per matrix = 256 threads * 2 float4.
    const int ak  = (tid & 3) << 2;   // k offset within BK: 0,4,8,12
    const int ar0 = tid >> 2;         // rows 0..63
    const int ar1 = ar0 + 64;         // rows 64..127

    const float* Ag0 = A + (size_t)(m_base + ar0) * NPIX + ak;
    const float* Ag1 = A + (size_t)(m_base + ar1) * NPIX + ak;
    const float* Bg0 = B + (size_t)(n_base + ar0) * NPIX + ak;
    const float* Bg1 = B + (size_t)(n_base + ar1) * NPIX + ak;

    // Prologue: tile 0 -> smem[0]
    {
        float4 a0 = *(const float4*)(Ag0);
        float4 a1 = *(const float4*)(Ag1);
        float4 b0 = *(const float4*)(Bg0);
        float4 b1 = *(const float4*)(Bg1);
        As[0][ak + 0][ar0] = a0.x; As[0][ak + 1][ar0] = a0.y;
        As[0][ak + 2][ar0] = a0.z; As[0][ak + 3][ar0] = a0.w;
        As[0][ak + 0][ar1] = a1.x; As[0][ak + 1][ar1] = a1.y;
        As[0][ak + 2][ar1] = a1.z; As[0][ak + 3][ar1] = a1.w;
        Bs[0][ak + 0][ar0] = b0.x; Bs[0][ak + 1][ar0] = b0.y;
        Bs[0][ak + 2][ar0] = b0.z; Bs[0][ak + 3][ar0] = b0.w;
        Bs[0][ak + 0][ar1] = b1.x; Bs[0][ak + 1][ar1] = b1.y;
        Bs[0][ak + 2][ar1] = b1.z; Bs[0][ak + 3][ar1] = b1.w;
    }
    __syncthreads();

    const int m0 = (tid >> 4) << 3;   // 0..120
    const int n0 = (tid & 15) << 3;   // 0..120

    float acc[8][8];
#pragma unroll
    for (int i = 0; i < 8; i++)
#pragma unroll
        for (int j = 0; j < 8; j++) acc[i][j] = 0.f;

    const int NT = NPIX / BK;  // 100
    int buf = 0;
    for (int t = 0; t < NT; t++) {
        float4 na0, na1, nb0, nb1;
        const bool has_next = (t + 1 < NT);
        if (has_next) {
            int off = (t + 1) * BK;
            na0 = *(const float4*)(Ag0 + off);
            na1 = *(const float4*)(Ag1 + off);
            nb0 = *(const float4*)(Bg0 + off);
            nb1 = *(const float4*)(Bg1 + off);
        }
#pragma unroll
        for (int kk = 0; kk < BK; kk++) {
            float4 av0 = *(const float4*)&As[buf][kk][m0];
            float4 av1 = *(const float4*)&As[buf][kk][m0 + 4];
            float4 bv0 = *(const float4*)&Bs[buf][kk][n0];
            float4 bv1 = *(const float4*)&Bs[buf][kk][n0 + 4];
            float am[8] = {av0.x, av0.y, av0.z, av0.w, av1.x, av1.y, av1.z, av1.w};
            float bn[8] = {bv0.x, bv0.y, bv0.z, bv0.w, bv1.x, bv1.y, bv1.z, bv1.w};
#pragma unroll
            for (int i = 0; i < 8; i++)
#pragma unroll
                for (int j = 0; j < 8; j++)
                    acc[i][j] = fmaf(am[i], bn[j], acc[i][j]);
        }
        if (has_next) {
            int nb = buf ^ 1;
            As[nb][ak + 0][ar0] = na0.x; As[nb][ak + 1][ar0] = na0.y;
            As[nb][ak + 2][ar0] = na0.z; As[nb][ak + 3][ar0] = na0.w;
            As[nb][ak + 0][ar1] = na1.x; As[nb][ak + 1][ar1] = na1.y;
            As[nb][ak + 2][ar1] = na1.z; As[nb][ak + 3][ar1] = na1.w;
            Bs[nb][ak + 0][ar0] = nb0.x; Bs[nb][ak + 1][ar0] = nb0.y;
            Bs[nb][ak + 2][ar0] = nb0.z; Bs[nb][ak + 3][ar0] = nb0.w;
            Bs[nb][ak + 0][ar1] = nb1.x; Bs[nb][ak + 1][ar1] = nb1.y;
            Bs[nb][ak + 2][ar1] = nb1.z; Bs[nb][ak + 3][ar1] = nb1.w;
            buf = nb;
        }
        __syncthreads();
    }

    // Epilogue: apply centering correction + normalization, write cos matrix.
    float mqv[8], iqv[8], mdv[8], idv[8];
#pragma unroll
    for (int i = 0; i < 8; i++) {
        mqv[i] = g_mq[m_base + m0 + i];
        iqv[i] = g_iq[m_base + m0 + i];
        mdv[i] = g_md[n_base + n0 + i];
        idv[i] = g_id[n_base + n0 + i];
    }
#pragma unroll
    for (int i = 0; i < 8; i++) {
        float* dst = &g_cos[(size_t)(m_base + m0 + i) * NDICT + (n_base + n0)];
        float corr = (float)NPIX * mqv[i];
        float4 o0, o1;
        o0.x = (acc[i][0] - corr * mdv[0]) * iqv[i] * idv[0];
        o0.y = (acc[i][1] - corr * mdv[1]) * iqv[i] * idv[1];
        o0.z = (acc[i][2] - corr * mdv[2]) * iqv[i] * idv[2];
        o0.w = (acc[i][3] - corr * mdv[3]) * iqv[i] * idv[3];
        o1.x = (acc[i][4] - corr * mdv[4]) * iqv[i] * idv[4];
        o1.y = (acc[i][5] - corr * mdv[5]) * iqv[i] * idv[5];
        o1.z = (acc[i][6] - corr * mdv[6]) * iqv[i] * idv[6];
        o1.w = (acc[i][7] - corr * mdv[7]) * iqv[i] * idv[7];
        *(float4*)dst = o0;
        *(float4*)(dst + 4) = o1;
    }
}

// ---------------------------------------------------------------------------
// Per-row top-10 over 65536 cos values. One block per experimental row.
// Per-thread branchless sorted insertion into 10 registers, then smem dump
// (2560 candidates) and 10 rounds of block-wide argmax with JAX tie-breaking
// (higher value wins; on exact tie, smaller dictionary index wins).
// Output layout (float32): [ang 2048*10][idx 2048*10][orient 2048*10*4]
// ---------------------------------------------------------------------------
__global__ void topk_kernel(const float* __restrict__ so3, float* __restrict__ out) {
    const int row = blockIdx.x;
    const int tid = threadIdx.x;
    const float* c = g_cos + (size_t)row * NDICT;

    float tv[KTOP];
    int   ti[KTOP];
#pragma unroll
    for (int i = 0; i < KTOP; i++) { tv[i] = -3.0f; ti[i] = 0x7fffffff; }

    for (int i = tid; i < NDICT; i += blockDim.x) {
        float v = c[i];
        if (v > tv[KTOP - 1]) {
            // shift entries smaller than v down by one (reads originals: p desc)
#pragma unroll
            for (int p = KTOP - 1; p >= 1; p--) {
                bool mv = (tv[p - 1] < v);
                if (mv) { tv[p] = tv[p - 1]; ti[p] = ti[p - 1]; }
            }
            // insert at first slot whose value < v
            bool placed = false;
#pragma unroll
            for (int p = 0; p < KTOP; p++) {
                if (!placed && tv[p] < v) { tv[p] = v; ti[p] = i; placed = true; }
            }
        }
    }

    __shared__ float sval[256 * KTOP];
    __shared__ int   sidx[256 * KTOP];
    __shared__ float rv[256];
    __shared__ int   ri[256];
#pragma unroll
    for (int j = 0; j < KTOP; j++) {
        sval[tid * KTOP + j] = tv[j];
        sidx[tid * KTOP + j] = ti[j];
    }
    __syncthreads();

    for (int r = 0; r < KTOP; r++) {
        // local argmax over this thread's 10 candidates
        float bv = -4.0f; int bi = 0x7fffffff;
        for (int j = 0; j < KTOP; j++) {
            float v = sval[tid * KTOP + j];
            int   x = sidx[tid * KTOP + j];
            if (v > bv || (v == bv && x < bi)) { bv = v; bi = x; }
        }
        rv[tid] = bv; ri[tid] = bi;
        __syncthreads();
        for (int s = 128; s > 0; s >>= 1) {
            if (tid < s) {
                float v2 = rv[tid + s]; int i2 = ri[tid + s];
                if (v2 > rv[tid] || (v2 == rv[tid] && i2 < ri[tid])) {
                    rv[tid] = v2; ri[tid] = i2;
                }
            }
            __syncthreads();
        }
        float wv = rv[0];
        int   wi = ri[0];
        // consume winner
        for (int j = 0; j < KTOP; j++)
            if (sidx[tid * KTOP + j] == wi) sval[tid * KTOP + j] = -4.0f;
        if (tid == 0) {
            float cc = fminf(fmaxf(wv, -1.0f), 1.0f);
            out[(size_t)row * KTOP + r] = acosf(cc);
            out[(size_t)NEXP * KTOP + (size_t)row * KTOP + r] = (float)wi;
            const float* q = so3 + (size_t)wi * 4;
            float* od = out + 2 * (size_t)NEXP * KTOP + ((size_t)row * KTOP + r) * 4;
            od[0] = q[0]; od[1] = q[1]; od[2] = q[2]; od[3] = q[3];
        }
        __syncthreads();
    }
}

extern "C" void kernel_launch(void* const* d_in, const int* in_sizes, int n_in,
                              void* d_out, int out_size) {
    const float* Q   = (const float*)d_in[0];  // experimental_data [2048,1600]
    const float* P   = (const float*)d_in[1];  // patterns          [65536,1600]
    const float* SO3 = (const float*)d_in[2];  // so3_samples_fz    [65536,4]
    float* out = (float*)d_out;

    rowstats_kernel<<<NEXP, 256>>>(Q, 0);
    rowstats_kernel<<<NDICT, 256>>>(P, 1);

    dim3 grid(NDICT / BN, NEXP / BM);  // (512, 16)
    gemm_kernel<<<grid, 256>>>(Q, P);

    topk_kernel<<<NEXP, 256>>>(SO3, out);
}

// round 6
// speedup vs baseline: 2.3274x; 2.3274x over previous
#include <cuda_runtime.h>
#include <cuda_fp16.h>
#include <cstdint>

#define NEXP 2048
#define NDICT 65536
#define NPIX 1600
#define KTOP 10
#define NCAND 16
#define BM 128
#define BN 256
#define NST 50                 // k-stages of 32 fp32 values
#define NCHUNK (NDICT / 64)    // 1024 candidate chunks per row
#define STAGE_BYTES 49152      // (128+256) rows * 128B
#define SMEM_DYN (3 * STAGE_BYTES)

typedef unsigned long long u64;

__device__ __half g_Qs[(size_t)NEXP * 2 * NPIX];   // [row][chunk:{hi32|lo32} f16]
__device__ __half g_Ps[(size_t)NDICT * 2 * NPIX];
__device__ float g_mq[NEXP], g_iq[NEXP], g_md[NDICT], g_id[NDICT];
__device__ u64 g_cand[(size_t)NEXP * NCHUNK * KTOP];
__device__ int g_top16[(size_t)NEXP * NCAND];

__device__ __forceinline__ uint32_t s2u(const void* p) {
    uint32_t a;
    asm("{ .reg .u64 t; cvta.to.shared.u64 t, %1; cvt.u32.u64 %0, t; }" : "=r"(a) : "l"(p));
    return a;
}
#define LDSM4(r, addr) asm volatile( \
    "ldmatrix.sync.aligned.m8n8.x4.shared.b16 {%0,%1,%2,%3}, [%4];" \
    : "=r"((r)[0]), "=r"((r)[1]), "=r"((r)[2]), "=r"((r)[3]) : "r"(addr))
#define MMA(d, a, b0, b1) asm volatile( \
    "mma.sync.aligned.m16n8k16.row.col.f32.f16.f16.f32 " \
    "{%0,%1,%2,%3},{%4,%5,%6,%7},{%8,%9},{%0,%1,%2,%3};" \
    : "+f"((d)[0]), "+f"((d)[1]), "+f"((d)[2]), "+f"((d)[3]) \
    : "r"((a)[0]), "r"((a)[1]), "r"((a)[2]), "r"((a)[3]), "r"(b0), "r"(b1))
#define CPA16(dst, src) asm volatile( \
    "cp.async.cg.shared.global [%0], [%1], 16;" :: "r"(dst), "l"(src) : "memory")

__device__ __forceinline__ u64 pack_vi(float v, int idx) {
    uint32_t ub = __float_as_uint(v);
    ub = (ub & 0x80000000u) ? ~ub : (ub | 0x80000000u);
    return ((u64)ub << 32) | (uint32_t)(~(uint32_t)idx);
}

// fp32 -> split f16 [hi(32)|lo(32)] per 32-k chunk, plus row stats.
// NOTE: the stats arithmetic here is bitwise-identical to the R1 rowstats
// kernel (same stride-256 loop order, same shuffle sequence, same 8-way sum).
__global__ void convert_kernel(const float* __restrict__ X, int which) {
    const int row = blockIdx.x, tid = threadIdx.x;
    const float* x = X + (size_t)row * NPIX;
    __half* o = (which ? g_Ps : g_Qs) + (size_t)row * 2 * NPIX;
    float s = 0.f, s2 = 0.f;
    for (int i = tid; i < NPIX; i += 256) {
        float f = x[i];
        s += f; s2 += f * f;
        __half hi = __float2half_rn(f);
        __half lo = __float2half_rn(f - __half2float(hi));
        int c = i >> 5, j = i & 31;
        o[(size_t)c * 64 + j] = hi;
        o[(size_t)c * 64 + 32 + j] = lo;
    }
#pragma unroll
    for (int off = 16; off > 0; off >>= 1) {
        s  += __shfl_down_sync(0xffffffffu, s, off);
        s2 += __shfl_down_sync(0xffffffffu, s2, off);
    }
    __shared__ float sh_s[8], sh_s2[8];
    int w = tid >> 5, l = tid & 31;
    if (l == 0) { sh_s[w] = s; sh_s2[w] = s2; }
    __syncthreads();
    if (tid == 0) {
        float ts = 0.f, ts2 = 0.f;
#pragma unroll
        for (int i = 0; i < 8; i++) { ts += sh_s[i]; ts2 += sh_s2[i]; }
        float m = ts / (float)NPIX;
        float inv = rsqrtf(ts2 - m * ts);
        if (which) { g_md[row] = m; g_id[row] = inv; }
        else       { g_mq[row] = m; g_iq[row] = inv; }
    }
}

// 3xFP16 split GEMM via mma.sync + fused cos epilogue + per-chunk top-10.
// Used for SELECTION only (top-16 membership); ranking redone exactly later.
__global__ void __launch_bounds__(512, 1) gemm_kernel() {
    extern __shared__ uint8_t dsm[];
    __shared__ float2 s_nd[BN];

    const int tid = threadIdx.x, lane = tid & 31, wid = tid >> 5;
    const int wm = wid & 3, wn = wid >> 2;
    const int m_base = blockIdx.x * BM, n_base = blockIdx.y * BN;
    const uint32_t sbase = s2u(dsm);

    uint32_t dstoff[6], srcoff[6];
#pragma unroll
    for (int jj = 0; jj < 6; jj++) {
        int seg = tid + jj * 512;
        int row = seg >> 3, s8 = seg & 7;
        dstoff[jj] = (uint32_t)(row * 128) + (((uint32_t)(s8 * 16)) ^ ((row & 7) << 4));
        srcoff[jj] = (jj < 2 ? (uint32_t)(m_base + row)
                             : (uint32_t)(n_base + row - 128)) * 6400u + (uint32_t)(s8 * 16);
    }
    const char* qb = (const char*)g_Qs;
    const char* pb = (const char*)g_Ps;

    const uint32_t xorL  = (uint32_t)(lane & 7) << 4;
    const uint32_t halfA = (uint32_t)(lane >> 4) << 4;
    const uint32_t halfB = (uint32_t)((lane >> 3) & 1) << 4;
    const uint32_t aoff0 = (uint32_t)(32 * wm + (lane & 15)) * 128u;
    const uint32_t aoff1 = aoff0 + 16 * 128u;
    uint32_t boff[4];
#pragma unroll
    for (int j = 0; j < 4; j++)
        boff[j] = 16384u + (uint32_t)(64 * wn + 16 * j + (lane & 7) + 8 * ((lane >> 4) & 1)) * 128u;

    float acc[2][8][4];
#pragma unroll
    for (int i = 0; i < 2; i++)
#pragma unroll
        for (int j = 0; j < 8; j++)
#pragma unroll
            for (int k = 0; k < 4; k++) acc[i][j][k] = 0.f;

#pragma unroll
    for (int p = 0; p < 2; p++) {
        uint32_t sb = sbase + p * STAGE_BYTES;
#pragma unroll
        for (int jj = 0; jj < 6; jj++)
            CPA16(sb + dstoff[jj], (jj < 2 ? qb : pb) + srcoff[jj] + (size_t)p * 128);
        asm volatile("cp.async.commit_group;" ::: "memory");
    }

    for (int t = 0; t < NST; t++) {
        asm volatile("cp.async.wait_group 1;" ::: "memory");
        __syncthreads();
        if (t + 2 < NST) {
            int p = t + 2;
            uint32_t sb = sbase + (p % 3) * STAGE_BYTES;
#pragma unroll
            for (int jj = 0; jj < 6; jj++)
                CPA16(sb + dstoff[jj], (jj < 2 ? qb : pb) + srcoff[jj] + (size_t)p * 128);
        }
        asm volatile("cp.async.commit_group;" ::: "memory");

        const uint32_t sb = sbase + (t % 3) * STAGE_BYTES;
#pragma unroll
        for (int c6 = 0; c6 < 6; c6++) {
            const uint32_t tA = (c6 >= 4) ? 64u : 0u;
            const uint32_t tB = (c6 == 2 || c6 == 3) ? 64u : 0u;
            const uint32_t sk = (c6 & 1) ? 32u : 0u;
            const uint32_t lowA = (tA | sk | halfA) ^ xorL;
            const uint32_t lowB = (tB | sk | halfB) ^ xorL;
            uint32_t a0[4], a1[4];
            LDSM4(a0, sb + aoff0 + lowA);
            LDSM4(a1, sb + aoff1 + lowA);
#pragma unroll
            for (int j = 0; j < 4; j++) {
                uint32_t b[4];
                LDSM4(b, sb + boff[j] + lowB);
                MMA(acc[0][2 * j],     a0, b[0], b[1]);
                MMA(acc[0][2 * j + 1], a0, b[2], b[3]);
                MMA(acc[1][2 * j],     a1, b[0], b[1]);
                MMA(acc[1][2 * j + 1], a1, b[2], b[3]);
            }
        }
    }
    __syncthreads();

    float* cbuf = (float*)dsm;
#pragma unroll
    for (int mi = 0; mi < 2; mi++)
#pragma unroll
        for (int nf = 0; nf < 8; nf++) {
            int r = 32 * wm + 16 * mi + (lane >> 2);
            int c = 64 * wn + 8 * nf + 2 * (lane & 3);
            cbuf[r * 264 + c]           = acc[mi][nf][0];
            cbuf[r * 264 + c + 1]       = acc[mi][nf][1];
            cbuf[(r + 8) * 264 + c]     = acc[mi][nf][2];
            cbuf[(r + 8) * 264 + c + 1] = acc[mi][nf][3];
        }
    if (tid < BN) {
        int n = n_base + tid;
        float idv = g_id[n];
        s_nd[tid] = make_float2(idv, g_md[n] * idv);
    }
    __syncthreads();

    const int row = tid >> 2, chunk = tid & 3;
    const int grow = m_base + row;
    const float iqv = g_iq[grow];
    const float cmq = (float)NPIX * g_mq[grow];
    u64 top[KTOP];
#pragma unroll
    for (int i = 0; i < KTOP; i++) top[i] = 0ULL;

    const int cb = 64 * chunk;
#pragma unroll 8
    for (int jj = 0; jj < 64; jj++) {
        int col = cb + jj;
        float2 nd = s_nd[col];
        float v = (cbuf[row * 264 + col] * nd.x - cmq * nd.y) * iqv;
        u64 p = pack_vi(v, n_base + col);
        if (p > top[KTOP - 1]) {
#pragma unroll
            for (int q = KTOP - 1; q >= 1; q--)
                if (top[q - 1] < p) top[q] = top[q - 1];
            bool placed = false;
#pragma unroll
            for (int q = 0; q < KTOP; q++)
                if (!placed && top[q] < p) { top[q] = p; placed = true; }
        }
    }
    u64* dst = g_cand + ((size_t)grow * NCHUNK + (size_t)blockIdx.y * 4 + chunk) * KTOP;
#pragma unroll
    for (int i = 0; i < KTOP; i++) dst[i] = top[i];
}

// Merge 1024 chunk-lists per row -> top-16 candidate INDICES (selection only).
__global__ void merge16_kernel() {
    const int row = blockIdx.x, tid = threadIdx.x;  // 256 threads
    __shared__ u64 c[256 * NCAND];
    __shared__ u64 red[256];

    u64 top[NCAND];
#pragma unroll
    for (int i = 0; i < NCAND; i++) top[i] = 0ULL;
    const u64* src = g_cand + ((size_t)row * NCHUNK + (size_t)tid * 4) * KTOP;
    for (int l = 0; l < 4; l++)
        for (int j = 0; j < KTOP; j++) {
            u64 p = src[l * KTOP + j];
            if (p > top[NCAND - 1]) {
#pragma unroll
                for (int q = NCAND - 1; q >= 1; q--)
                    if (top[q - 1] < p) top[q] = top[q - 1];
                bool placed = false;
#pragma unroll
                for (int q = 0; q < NCAND; q++)
                    if (!placed && top[q] < p) { top[q] = p; placed = true; }
            }
        }
#pragma unroll
    for (int j = 0; j < NCAND; j++) c[tid * NCAND + j] = top[j];
    int cur = 0;
    __syncthreads();

    for (int r = 0; r < NCAND; r++) {
        u64 v = (cur < NCAND) ? c[tid * NCAND + cur] : 0ULL;
        red[tid] = v;
        __syncthreads();
        for (int s = 128; s > 0; s >>= 1) {
            if (tid < s && red[tid + s] > red[tid]) red[tid] = red[tid + s];
            __syncthreads();
        }
        u64 w = red[0];
        if (v == w && cur < NCAND) cur++;
        if (tid == 0)
            g_top16[(size_t)row * NCAND + r] = (int)(~(uint32_t)(w & 0xffffffffu));
        __syncthreads();
    }
}

// EXACT rescore: one thread per candidate, single fp32 fmaf chain over k
// ascending on RAW inputs + R1's exact epilogue arithmetic. This reproduces
// the R1 (passing) kernel's cos values bitwise, so the final ranking matches
// the reference's observed ordering including near-tie pairs.
__global__ void __launch_bounds__(256, 4)
rescore_kernel(const float* __restrict__ Q, const float* __restrict__ P,
               const float* __restrict__ so3, float* __restrict__ out) {
    const int tid = threadIdx.x;
    const int rloc = tid >> 4, cand = tid & 15;
    const int row = blockIdx.x * 16 + rloc;
    const int idx = g_top16[(size_t)row * NCAND + cand];

    const float* q = Q + (size_t)row * NPIX;
    const float* p = P + (size_t)idx * NPIX;
    float acc = 0.f;
#pragma unroll 8
    for (int k = 0; k < NPIX; k++)
        acc = fmaf(q[k], p[k], acc);

    // R1 epilogue, same association: ((acc - (1600*mq)*md) * iq) * id
    float corr = (float)NPIX * g_mq[row];
    float v = (acc - corr * g_md[idx]) * g_iq[row] * g_id[idx];

    __shared__ u64 sp[256];
    sp[tid] = pack_vi(v, idx);
    __syncthreads();

    u64 mine = sp[tid];
    int rank = 0;
#pragma unroll
    for (int j = 0; j < NCAND; j++) rank += (sp[rloc * 16 + j] > mine);
    if (rank < KTOP) {
        float cc = fminf(fmaxf(v, -1.0f), 1.0f);
        out[(size_t)row * KTOP + rank] = acosf(cc);
        out[(size_t)NEXP * KTOP + (size_t)row * KTOP + rank] = (float)idx;
        const float* qt = so3 + (size_t)idx * 4;
        float* od = out + 2 * (size_t)NEXP * KTOP + ((size_t)row * KTOP + rank) * 4;
        od[0] = qt[0]; od[1] = qt[1]; od[2] = qt[2]; od[3] = qt[3];
    }
}

extern "C" void kernel_launch(void* const* d_in, const int* in_sizes, int n_in,
                              void* d_out, int out_size) {
    const float* Q   = (const float*)d_in[0];
    const float* P   = (const float*)d_in[1];
    const float* SO3 = (const float*)d_in[2];
    float* out = (float*)d_out;

    cudaFuncSetAttribute(gemm_kernel, cudaFuncAttributeMaxDynamicSharedMemorySize, SMEM_DYN);

    convert_kernel<<<NEXP, 256>>>(Q, 0);
    convert_kernel<<<NDICT, 256>>>(P, 1);

    dim3 grid(NEXP / BM, NDICT / BN);  // (16, 256)
    gemm_kernel<<<grid, 512, SMEM_DYN>>>();

    merge16_kernel<<<NEXP, 256>>>();
    rescore_kernel<<<NEXP / 16, 256>>>(Q, P, SO3, out);
}

// round 7
// speedup vs baseline: 4.2350x; 1.8196x over previous
#include <cuda_runtime.h>
#include <cuda_fp16.h>
#include <cstdint>

#define NEXP 2048
#define NDICT 65536
#define NPIX 1600
#define KTOP 10
#define NCAND 16
#define BM 128
#define BN 256
#define NST 25                 // k-stages of 64 fp32 values (hi-f16 only)
#define NTILE (NDICT / BN)     // 256 candidate tiles per row
#define STAGE_BYTES 49152      // (128+256) rows * 128B
#define SMEM_DYN (3 * STAGE_BYTES)

typedef unsigned long long u64;

__device__ __half g_Qs[(size_t)NEXP * NPIX];   // hi-f16 only, row-major
__device__ __half g_Ps[(size_t)NDICT * NPIX];
__device__ float g_mq[NEXP], g_iq[NEXP], g_md[NDICT], g_id[NDICT];
__device__ u64 g_cand[(size_t)NEXP * NTILE * KTOP];   // 42 MB
__device__ int g_top16[(size_t)NEXP * NCAND];

__device__ __forceinline__ uint32_t s2u(const void* p) {
    uint32_t a;
    asm("{ .reg .u64 t; cvta.to.shared.u64 t, %1; cvt.u32.u64 %0, t; }" : "=r"(a) : "l"(p));
    return a;
}
#define LDSM4(r, addr) asm volatile( \
    "ldmatrix.sync.aligned.m8n8.x4.shared.b16 {%0,%1,%2,%3}, [%4];" \
    : "=r"((r)[0]), "=r"((r)[1]), "=r"((r)[2]), "=r"((r)[3]) : "r"(addr))
#define MMA(d, a, b0, b1) asm volatile( \
    "mma.sync.aligned.m16n8k16.row.col.f32.f16.f16.f32 " \
    "{%0,%1,%2,%3},{%4,%5,%6,%7},{%8,%9},{%0,%1,%2,%3};" \
    : "+f"((d)[0]), "+f"((d)[1]), "+f"((d)[2]), "+f"((d)[3]) \
    : "r"((a)[0]), "r"((a)[1]), "r"((a)[2]), "r"((a)[3]), "r"(b0), "r"(b1))
#define CPA16(dst, src) asm volatile( \
    "cp.async.cg.shared.global [%0], [%1], 16;" :: "r"(dst), "l"(src) : "memory")

__device__ __forceinline__ u64 pack_vi(float v, int idx) {
    uint32_t ub = __float_as_uint(v);
    ub = (ub & 0x80000000u) ? ~ub : (ub | 0x80000000u);
    return ((u64)ub << 32) | (uint32_t)(~(uint32_t)idx);
}
__device__ __forceinline__ void ins10(u64* top, u64 p) {
    if (p > top[KTOP - 1]) {
#pragma unroll
        for (int q = KTOP - 1; q >= 1; q--)
            if (top[q - 1] < p) top[q] = top[q - 1];
        bool placed = false;
#pragma unroll
        for (int q = 0; q < KTOP; q++)
            if (!placed && top[q] < p) { top[q] = p; placed = true; }
    }
}

// fp32 -> hi-f16 (selection precision) + row stats. Stats arithmetic is
// bitwise-identical to the R1 rowstats kernel (same loop/shuffle/final-sum).
__global__ void convert_kernel(const float* __restrict__ X, int which) {
    const int row = blockIdx.x, tid = threadIdx.x;
    const float* x = X + (size_t)row * NPIX;
    __half* o = (which ? g_Ps : g_Qs) + (size_t)row * NPIX;
    float s = 0.f, s2 = 0.f;
    for (int i = tid; i < NPIX; i += 256) {
        float f = x[i];
        s += f; s2 += f * f;
        o[i] = __float2half_rn(f);
    }
#pragma unroll
    for (int off = 16; off > 0; off >>= 1) {
        s  += __shfl_down_sync(0xffffffffu, s, off);
        s2 += __shfl_down_sync(0xffffffffu, s2, off);
    }
    __shared__ float sh_s[8], sh_s2[8];
    int w = tid >> 5, l = tid & 31;
    if (l == 0) { sh_s[w] = s; sh_s2[w] = s2; }
    __syncthreads();
    if (tid == 0) {
        float ts = 0.f, ts2 = 0.f;
#pragma unroll
        for (int i = 0; i < 8; i++) { ts += sh_s[i]; ts2 += sh_s2[i]; }
        float m = ts / (float)NPIX;
        float inv = rsqrtf(ts2 - m * ts);
        if (which) { g_md[row] = m; g_id[row] = inv; }
        else       { g_mq[row] = m; g_iq[row] = inv; }
    }
}

// 1-term hi-f16 GEMM (selection only) + fused cos epilogue + per-row top-10.
// CTA 128x256, 512 threads, 16 warps (warp tile 32x64), 3-stage cp.async.
__global__ void __launch_bounds__(512, 1) gemm_kernel() {
    extern __shared__ uint8_t dsm[];
    __shared__ float2 s_nd[BN];

    const int tid = threadIdx.x, lane = tid & 31, wid = tid >> 5;
    const int wm = wid & 3, wn = wid >> 2;
    const int m_base = blockIdx.x * BM, n_base = blockIdx.y * BN;
    const uint32_t sbase = s2u(dsm);

    // ---- producer: 6 x 16B cp.async per thread per stage (128B per row) ----
    uint32_t dstoff[6], srcoff[6];
#pragma unroll
    for (int jj = 0; jj < 6; jj++) {
        int seg = tid + jj * 512;              // 0..3071
        int row = seg >> 3, s8 = seg & 7;      // rows 0..127 A, 128..383 B
        dstoff[jj] = (uint32_t)(row * 128) + (((uint32_t)(s8 * 16)) ^ ((row & 7) << 4));
        srcoff[jj] = (jj < 2 ? (uint32_t)(m_base + row)
                             : (uint32_t)(n_base + row - 128)) * 3200u + (uint32_t)(s8 * 16);
    }
    const char* qb = (const char*)g_Qs;
    const char* pb = (const char*)g_Ps;

    const uint32_t xorL  = (uint32_t)(lane & 7) << 4;
    const uint32_t halfA = (uint32_t)(lane >> 4) << 4;
    const uint32_t halfB = (uint32_t)((lane >> 3) & 1) << 4;
    const uint32_t aoff0 = (uint32_t)(32 * wm + (lane & 15)) * 128u;
    const uint32_t aoff1 = aoff0 + 16 * 128u;
    uint32_t boff[4];
#pragma unroll
    for (int j = 0; j < 4; j++)
        boff[j] = 16384u + (uint32_t)(64 * wn + 16 * j + (lane & 7) + 8 * ((lane >> 4) & 1)) * 128u;

    float acc[2][8][4];
#pragma unroll
    for (int i = 0; i < 2; i++)
#pragma unroll
        for (int j = 0; j < 8; j++)
#pragma unroll
            for (int k = 0; k < 4; k++) acc[i][j][k] = 0.f;

#pragma unroll
    for (int p = 0; p < 2; p++) {
        uint32_t sb = sbase + p * STAGE_BYTES;
#pragma unroll
        for (int jj = 0; jj < 6; jj++)
            CPA16(sb + dstoff[jj], (jj < 2 ? qb : pb) + srcoff[jj] + (size_t)p * 128);
        asm volatile("cp.async.commit_group;" ::: "memory");
    }

    for (int t = 0; t < NST; t++) {
        asm volatile("cp.async.wait_group 1;" ::: "memory");
        __syncthreads();
        if (t + 2 < NST) {
            int p = t + 2;
            uint32_t sb = sbase + (p % 3) * STAGE_BYTES;
#pragma unroll
            for (int jj = 0; jj < 6; jj++)
                CPA16(sb + dstoff[jj], (jj < 2 ? qb : pb) + srcoff[jj] + (size_t)p * 128);
        }
        asm volatile("cp.async.commit_group;" ::: "memory");

        const uint32_t sb = sbase + (t % 3) * STAGE_BYTES;
#pragma unroll
        for (int s = 0; s < 4; s++) {          // 4 k16-steps per 128B stage
            const uint32_t sk = 32u * s;
            const uint32_t lowA = (sk | halfA) ^ xorL;
            const uint32_t lowB = (sk | halfB) ^ xorL;
            uint32_t a0[4], a1[4];
            LDSM4(a0, sb + aoff0 + lowA);
            LDSM4(a1, sb + aoff1 + lowA);
#pragma unroll
            for (int j = 0; j < 4; j++) {
                uint32_t b[4];
                LDSM4(b, sb + boff[j] + lowB);
                MMA(acc[0][2 * j],     a0, b[0], b[1]);
                MMA(acc[0][2 * j + 1], a0, b[2], b[3]);
                MMA(acc[1][2 * j],     a1, b[0], b[1]);
                MMA(acc[1][2 * j + 1], a1, b[2], b[3]);
            }
        }
    }
    __syncthreads();

    // ---- epilogue: dump C tile to smem (stride 264 f32) ----
    float* cbuf = (float*)dsm;
#pragma unroll
    for (int mi = 0; mi < 2; mi++)
#pragma unroll
        for (int nf = 0; nf < 8; nf++) {
            int r = 32 * wm + 16 * mi + (lane >> 2);
            int c = 64 * wn + 8 * nf + 2 * (lane & 3);
            cbuf[r * 264 + c]           = acc[mi][nf][0];
            cbuf[r * 264 + c + 1]       = acc[mi][nf][1];
            cbuf[(r + 8) * 264 + c]     = acc[mi][nf][2];
            cbuf[(r + 8) * 264 + c + 1] = acc[mi][nf][3];
        }
    if (tid < BN) {
        int n = n_base + tid;
        float idv = g_id[n];
        s_nd[tid] = make_float2(idv, g_md[n] * idv);
    }
    __syncthreads();

    // ---- per (row, 64-col chunk) top-10 ----
    const int row = tid >> 2, chunk = tid & 3;
    const int grow = m_base + row;
    const float iqv = g_iq[grow];
    const float cmq = (float)NPIX * g_mq[grow];
    u64 top[KTOP];
#pragma unroll
    for (int i = 0; i < KTOP; i++) top[i] = 0ULL;

    const int cb = 64 * chunk;
#pragma unroll 8
    for (int jj = 0; jj < 64; jj++) {
        int col = cb + jj;
        float2 nd = s_nd[col];
        float v = (cbuf[row * 264 + col] * nd.x - cmq * nd.y) * iqv;
        ins10(top, pack_vi(v, n_base + col));
    }
    __syncthreads();   // all cbuf reads done; reuse smem for candidates

    u64* csm = (u64*)dsm;   // [512][KTOP] = 40 KB
#pragma unroll
    for (int i = 0; i < KTOP; i++) csm[tid * KTOP + i] = top[i];
    __syncthreads();

    // ---- 4->1 chunk merge per row, write one top-10 list per (row, tile) ----
    if (tid < BM) {
        u64 mtop[KTOP];
#pragma unroll
        for (int i = 0; i < KTOP; i++) mtop[i] = 0ULL;
        const u64* base = csm + (size_t)tid * 4 * KTOP;
        for (int c = 0; c < 4 * KTOP; c++) ins10(mtop, base[c]);
        u64* dst = g_cand + ((size_t)(m_base + tid) * NTILE + blockIdx.y) * KTOP;
#pragma unroll
        for (int i = 0; i < KTOP; i++) dst[i] = mtop[i];
    }
}

// Merge 256 tile-lists per row -> top-16 candidate INDICES (selection only).
__global__ void merge16_kernel() {
    const int row = blockIdx.x, tid = threadIdx.x;  // 256 threads
    __shared__ u64 c[256 * KTOP];
    __shared__ u64 red[256];

    const u64* src = g_cand + ((size_t)row * NTILE + tid) * KTOP;
#pragma unroll
    for (int j = 0; j < KTOP; j++) c[tid * KTOP + j] = src[j];  // sorted desc
    int cur = 0;
    __syncthreads();

    for (int r = 0; r < NCAND; r++) {
        u64 v = (cur < KTOP) ? c[tid * KTOP + cur] : 0ULL;
        red[tid] = v;
        __syncthreads();
        for (int s = 128; s > 0; s >>= 1) {
            if (tid < s && red[tid + s] > red[tid]) red[tid] = red[tid + s];
            __syncthreads();
        }
        u64 w = red[0];
        if (v == w && cur < KTOP) cur++;
        if (tid == 0)
            g_top16[(size_t)row * NCAND + r] = (int)(~(uint32_t)(w & 0xffffffffu));
        __syncthreads();
    }
}

// EXACT rescore (bitwise-replicates the R1 kernel's accumulation order):
// one thread per candidate, single fp32 fmaf chain over k ascending on RAW
// inputs + R1's exact epilogue. Reproduces reference-observed ordering.
__global__ void __launch_bounds__(256, 4)
rescore_kernel(const float* __restrict__ Q, const float* __restrict__ P,
               const float* __restrict__ so3, float* __restrict__ out) {
    const int tid = threadIdx.x;
    const int rloc = tid >> 4, cand = tid & 15;
    const int row = blockIdx.x * 16 + rloc;
    const int idx = g_top16[(size_t)row * NCAND + cand];

    const float* q = Q + (size_t)row * NPIX;
    const float* p = P + (size_t)idx * NPIX;
    float acc = 0.f;
#pragma unroll 8
    for (int k = 0; k < NPIX; k++)
        acc = fmaf(q[k], p[k], acc);

    float corr = (float)NPIX * g_mq[row];
    float v = (acc - corr * g_md[idx]) * g_iq[row] * g_id[idx];

    __shared__ u64 sp[256];
    sp[tid] = pack_vi(v, idx);
    __syncthreads();

    u64 mine = sp[tid];
    int rank = 0;
#pragma unroll
    for (int j = 0; j < NCAND; j++) rank += (sp[rloc * 16 + j] > mine);
    if (rank < KTOP) {
        float cc = fminf(fmaxf(v, -1.0f), 1.0f);
        out[(size_t)row * KTOP + rank] = acosf(cc);
        out[(size_t)NEXP * KTOP + (size_t)row * KTOP + rank] = (float)idx;
        const float* qt = so3 + (size_t)idx * 4;
        float* od = out + 2 * (size_t)NEXP * KTOP + ((size_t)row * KTOP + rank) * 4;
        od[0] = qt[0]; od[1] = qt[1]; od[2] = qt[2]; od[3] = qt[3];
    }
}

extern "C" void kernel_launch(void* const* d_in, const int* in_sizes, int n_in,
                              void* d_out, int out_size) {
    const float* Q   = (const float*)d_in[0];
    const float* P   = (const float*)d_in[1];
    const float* SO3 = (const float*)d_in[2];
    float* out = (float*)d_out;

    cudaFuncSetAttribute(gemm_kernel, cudaFuncAttributeMaxDynamicSharedMemorySize, SMEM_DYN);

    convert_kernel<<<NEXP, 256>>>(Q, 0);
    convert_kernel<<<NDICT, 256>>>(P, 1);

    dim3 grid(NEXP / BM, NDICT / BN);  // (16, 256)
    gemm_kernel<<<grid, 512, SMEM_DYN>>>();

    merge16_kernel<<<NEXP, 256>>>();
    rescore_kernel<<<NEXP / 16, 256>>>(Q, P, SO3, out);
}